// round 8
// baseline (speedup 1.0000x reference)
#include <cuda_runtime.h>
#include <stdint.h>

#define NC 4096   // concepts (= output cols)
#define CD 1024   // cdim
#define BT 4096   // batch rows
#define KS 256    // sampled per row

// Scratch (allocation-free rule: device global).
__device__ float g_s[NC];

// ---------------------------------------------------------------------------
// Kernel 1: (a) one warp per concept row computes s[row] = sum cb*attn
//           (b) every thread zerofills a slice of the 64MiB output.
// (a) and (b) are independent; reads overlap the write wall on the duplex
// memory path. Grid 512 x 256: warps 0..4095 <-> concept rows, zerofill is
// grid-strided (16 x st.global.v8 per thread).
// ---------------------------------------------------------------------------
__global__ __launch_bounds__(256) void dot_zero_kernel(
    const float* __restrict__ cb, const float* __restrict__ attn,
    float* __restrict__ out)
{
    const int t     = threadIdx.x;
    const int gtid  = blockIdx.x * 256 + t;
    const int row   = gtid >> 5;            // warp id == concept row (exactly 4096)
    const int lane  = t & 31;

    // ---- row dot product, loads front-batched for MLP ----
    {
        const float4* c4 = reinterpret_cast<const float4*>(cb   + (size_t)row * CD);
        const float4* a4 = reinterpret_cast<const float4*>(attn + (size_t)row * CD);
        float sum = 0.f;
        #pragma unroll
        for (int half = 0; half < 2; half++) {
            float4 c[4], a[4];
            #pragma unroll
            for (int i = 0; i < 4; i++) c[i] = c4[lane + (half * 4 + i) * 32];
            #pragma unroll
            for (int i = 0; i < 4; i++) a[i] = a4[lane + (half * 4 + i) * 32];
            #pragma unroll
            for (int i = 0; i < 4; i++)
                sum += c[i].x * a[i].x + c[i].y * a[i].y
                     + c[i].z * a[i].z + c[i].w * a[i].w;
        }
        #pragma unroll
        for (int o = 16; o > 0; o >>= 1)
            sum += __shfl_xor_sync(0xFFFFFFFFu, sum, o);
        if (lane == 0) g_s[row] = sum;
    }

    // ---- zerofill: 2M v8-units / 131072 threads = 16 per thread ----
    {
        float* base = out + (size_t)gtid * 8;
        #pragma unroll
        for (int i = 0; i < 16; i++) {
            asm volatile(
                "st.global.v8.f32 [%0], {%1,%1,%1,%1,%1,%1,%1,%1};"
                :: "l"(base + (size_t)i * 131072 * 8), "f"(0.f) : "memory");
        }
    }
}

// ---------------------------------------------------------------------------
// Kernel 2: sparse scatter. out[b, idx[b,k]] = s[idx[b,k]] for the 1M samples.
// Each thread: one int4 (4 indices, same batch row), 4 L1-hot s loads,
// 4 scattered 4B stores into L2-hot lines. Duplicates write equal values.
// ---------------------------------------------------------------------------
__global__ __launch_bounds__(256) void scatter_kernel(
    const int* __restrict__ idx, float* __restrict__ out)
{
#if (__CUDACC_VER_MAJOR__ >= 12)
    cudaGridDependencySynchronize();     // PDL: K1 writes visible
#endif
    const int gtid = blockIdx.x * 256 + threadIdx.x;   // 262144 threads
    const int4 v   = reinterpret_cast<const int4*>(idx)[gtid];
    const int  b   = gtid >> 6;                        // 64 int4 per row (KS=256)
    float* orow    = out + (size_t)b * NC;

    int a0 = v.x & (NC - 1), a1 = v.y & (NC - 1);
    int a2 = v.z & (NC - 1), a3 = v.w & (NC - 1);
    orow[a0] = g_s[a0];
    orow[a1] = g_s[a1];
    orow[a2] = g_s[a2];
    orow[a3] = g_s[a3];
}

extern "C" void kernel_launch(void* const* d_in, const int* in_sizes, int n_in,
                              void* d_out, int out_size)
{
    const float* cb   = (const float*)d_in[0];
    const float* attn = (const float*)d_in[1];
    const int*   idx  = (const int*)d_in[2];
    float*       out  = (float*)d_out;

    dot_zero_kernel<<<512, 256>>>(cb, attn, out);

    cudaLaunchConfig_t cfg = {};
    cfg.gridDim  = dim3(1024, 1, 1);
    cfg.blockDim = dim3(256, 1, 1);
    cudaLaunchAttribute attrs[1];
    attrs[0].id = cudaLaunchAttributeProgrammaticStreamSerialization;
    attrs[0].val.programmaticStreamSerializationAllowed = 1;
    cfg.attrs = attrs;
    cfg.numAttrs = 1;
    cudaLaunchKernelEx(&cfg, scatter_kernel, idx, out);
}

// round 10
// speedup vs baseline: 1.0833x; 1.0833x over previous
#include <cuda_runtime.h>
#include <stdint.h>

#define NC 4096   // concepts (= output cols)
#define CD 1024   // cdim
#define BT 4096   // batch rows
#define KS 256    // sampled per row
#define ROWS_PER_CTA 2

// Scratch (allocation-free rule: device globals).
__device__ float    g_s[NC];                  // 16 KB
__device__ unsigned g_mask[BT * (NC / 32)];   // 2 MB bitmask, 128 words/row

// ---------------------------------------------------------------------------
// Kernel 1 (prep): mask build for 8 batch rows + row-dots for 8 concept rows.
// ---------------------------------------------------------------------------
__global__ __launch_bounds__(256) void prep_kernel(
    const float* __restrict__ cb, const float* __restrict__ attn,
    const int* __restrict__ sampled_idx)
{
    __shared__ unsigned bm[8 * 128];   // 8 rows x 128 words = 4 KB

    const int t    = threadIdx.x;
    const int warp = t >> 5;
    const int lane = t & 31;

    reinterpret_cast<uint4*>(bm)[t] = make_uint4(0u, 0u, 0u, 0u);
    __syncthreads();

    // 8 rows' indices = 2048 contiguous ints = 512 int4; 2 per thread.
    {
        const int4* i4 = reinterpret_cast<const int4*>(
            sampled_idx + (size_t)blockIdx.x * 8 * KS);
        #pragma unroll
        for (int j = 0; j < 2; j++) {
            int p  = t + j * 256;
            int4 v = i4[p];
            int r  = p >> 6;
            int a  = v.x & (NC - 1);
            int b  = v.y & (NC - 1);
            int c  = v.z & (NC - 1);
            int d  = v.w & (NC - 1);
            atomicOr(&bm[r * 128 + (a >> 5)], 1u << (a & 31));
            atomicOr(&bm[r * 128 + (b >> 5)], 1u << (b & 31));
            atomicOr(&bm[r * 128 + (c >> 5)], 1u << (c & 31));
            atomicOr(&bm[r * 128 + (d >> 5)], 1u << (d & 31));
        }
    }

    // Row-dot, one warp per concept row, loads front-batched for MLP.
    {
        const int row = blockIdx.x * 8 + warp;
        const float4* c4 = reinterpret_cast<const float4*>(cb   + (size_t)row * CD);
        const float4* a4 = reinterpret_cast<const float4*>(attn + (size_t)row * CD);
        float4 c[8], a[8];
        #pragma unroll
        for (int i = 0; i < 8; i++) c[i] = c4[lane + i * 32];
        #pragma unroll
        for (int i = 0; i < 8; i++) a[i] = a4[lane + i * 32];
        float sum = 0.f;
        #pragma unroll
        for (int i = 0; i < 8; i++)
            sum += c[i].x * a[i].x + c[i].y * a[i].y
                 + c[i].z * a[i].z + c[i].w * a[i].w;
        #pragma unroll
        for (int o = 16; o > 0; o >>= 1)
            sum += __shfl_xor_sync(0xFFFFFFFFu, sum, o);
        if (lane == 0) g_s[row] = sum;
    }

    __syncthreads();
    reinterpret_cast<uint4*>(g_mask + (size_t)blockIdx.x * 1024)[t] =
        reinterpret_cast<const uint4*>(bm)[t];
}

// ---------------------------------------------------------------------------
// Kernel 2 (store): build 2 output rows in STATIC shared (32 KB, no attribute
// call needed), then push them out with cp.async.bulk (TMA store path —
// bypasses the LSU/L1 STG pipe). One barrier per CTA; stores async; grid 2048.
// ---------------------------------------------------------------------------
__global__ __launch_bounds__(256) void store_kernel(float* __restrict__ out)
{
    __shared__ float sbuf[ROWS_PER_CTA * NC];     // 32 KB static

    const int t    = threadIdx.x;
    const int row0 = blockIdx.x * ROWS_PER_CTA;

    // This thread's 16 s-values.
    float4 sv[4];
    const float4* g4 = reinterpret_cast<const float4*>(g_s);
    #pragma unroll
    for (int q = 0; q < 4; q++) sv[q] = g4[q * 256 + t];

    // Fill both row buffers (conflict-free: 16B lane stride).
    #pragma unroll
    for (int r = 0; r < ROWS_PER_CTA; r++) {
        const unsigned* mrow = g_mask + (size_t)(row0 + r) * 128;
        float4* buf4 = reinterpret_cast<float4*>(sbuf + r * NC);
        #pragma unroll
        for (int q = 0; q < 4; q++) {
            unsigned w = mrow[q * 32 + (t >> 3)];    // 8 threads/word broadcast
            unsigned b = w >> ((t & 7) * 4);
            float4 v;
            v.x = (b & 1u) ? sv[q].x : 0.f;
            v.y = (b & 2u) ? sv[q].y : 0.f;
            v.z = (b & 4u) ? sv[q].z : 0.f;
            v.w = (b & 8u) ? sv[q].w : 0.f;
            buf4[q * 256 + t] = v;
        }
    }
    __syncthreads();

    // Async bulk stores: 2 x 16 KB, issued by thread 0.
    if (t == 0) {
        asm volatile("fence.proxy.async.shared::cta;" ::: "memory");
        uint32_t sa;
        asm("{ .reg .u64 x; cvta.to.shared.u64 x, %1; cvt.u32.u64 %0, x; }"
            : "=r"(sa) : "l"(sbuf));
        #pragma unroll
        for (int r = 0; r < ROWS_PER_CTA; r++) {
            asm volatile(
                "cp.async.bulk.global.shared::cta.bulk_group [%0], [%1], %2;"
                :: "l"(out + (size_t)(row0 + r) * NC),
                   "r"(sa + r * NC * 4), "r"(NC * 4) : "memory");
        }
        asm volatile("cp.async.bulk.commit_group;" ::: "memory");
        asm volatile("cp.async.bulk.wait_group 0;" ::: "memory");
    }
}

extern "C" void kernel_launch(void* const* d_in, const int* in_sizes, int n_in,
                              void* d_out, int out_size)
{
    const float* cb   = (const float*)d_in[0];
    const float* attn = (const float*)d_in[1];
    const int*   idx  = (const int*)d_in[2];
    float*       out  = (float*)d_out;

    prep_kernel<<<NC / 8, 256>>>(cb, attn, idx);
    store_kernel<<<BT / ROWS_PER_CTA, 256>>>(out);
}

// round 11
// speedup vs baseline: 1.1751x; 1.0847x over previous
#include <cuda_runtime.h>
#include <stdint.h>

#define NC 4096   // concepts (= output cols)
#define CD 1024   // cdim
#define BT 4096   // batch rows
#define KS 256    // sampled per row

#define DOT_CTAS  512
#define ZERO_CTAS 1536
#define TOTAL_V8  ((BT * NC) / 8)            // 2M 32B-units
#define ZSTRIDE   (ZERO_CTAS * 256)

// Scratch (allocation-free rule: device global).
__device__ float g_s[NC];   // 16 KB

// ---------------------------------------------------------------------------
// Kernel 1: CTA-specialized.
//   bid <  DOT_CTAS : one warp per concept row -> s[row] (pure READ stream)
//   bid >= DOT_CTAS : grid-stride zerofill of the 64MiB output (pure WRITE)
// The two CTA classes are co-scheduled across SMs, so the 36MB read stream
// hides under the ~14us write wall instead of serializing after it.
// ---------------------------------------------------------------------------
__global__ __launch_bounds__(256) void dotzero_kernel(
    const float* __restrict__ cb, const float* __restrict__ attn,
    float* __restrict__ out)
{
    const int t = threadIdx.x;

    if (blockIdx.x < DOT_CTAS) {
        // ---- dot CTA: 8 warps, 8 concept rows, loads front-batched ----
        const int warp = t >> 5;
        const int lane = t & 31;
        const int row  = blockIdx.x * 8 + warp;

        const float4* c4 = reinterpret_cast<const float4*>(cb   + (size_t)row * CD);
        const float4* a4 = reinterpret_cast<const float4*>(attn + (size_t)row * CD);

        float4 c[8], a[8];
        #pragma unroll
        for (int i = 0; i < 8; i++) c[i] = c4[lane + i * 32];
        #pragma unroll
        for (int i = 0; i < 8; i++) a[i] = a4[lane + i * 32];

        float sum = 0.f;
        #pragma unroll
        for (int i = 0; i < 8; i++)
            sum += c[i].x * a[i].x + c[i].y * a[i].y
                 + c[i].z * a[i].z + c[i].w * a[i].w;

        #pragma unroll
        for (int o = 16; o > 0; o >>= 1)
            sum += __shfl_xor_sync(0xFFFFFFFFu, sum, o);
        if (lane == 0) g_s[row] = sum;
    } else {
        // ---- zero CTA: coalesced 32B stores, grid-strided ----
        const int zi = (blockIdx.x - DOT_CTAS) * 256 + t;
        for (int i = zi; i < TOTAL_V8; i += ZSTRIDE) {
            asm volatile(
                "st.global.v8.f32 [%0], {%1,%1,%1,%1,%1,%1,%1,%1};"
                :: "l"(out + (size_t)i * 8), "f"(0.f) : "memory");
        }
    }
}

// ---------------------------------------------------------------------------
// Kernel 2 (PDL): sparse scatter of the 1M nonzeros into L2-hot zeroed lines.
// out[b, idx[b,k]] = s[idx[b,k]]; duplicates write equal values (benign).
// Each thread: one int4 (4 indices of one batch row), 4 L1-hot s loads,
// 4 scattered 4B stores.
// ---------------------------------------------------------------------------
__global__ __launch_bounds__(256) void scatter_kernel(
    const int* __restrict__ idx, float* __restrict__ out)
{
#if (__CUDACC_VER_MAJOR__ >= 12)
    cudaGridDependencySynchronize();     // K1 writes visible before we start
#endif
    const int gtid = blockIdx.x * 256 + threadIdx.x;   // 262144 threads
    const int4 v   = reinterpret_cast<const int4*>(idx)[gtid];
    const int  b   = gtid >> 6;                        // 64 int4 per row (KS=256)
    float* orow    = out + (size_t)b * NC;

    const int a0 = v.x & (NC - 1), a1 = v.y & (NC - 1);
    const int a2 = v.z & (NC - 1), a3 = v.w & (NC - 1);
    orow[a0] = g_s[a0];
    orow[a1] = g_s[a1];
    orow[a2] = g_s[a2];
    orow[a3] = g_s[a3];
}

extern "C" void kernel_launch(void* const* d_in, const int* in_sizes, int n_in,
                              void* d_out, int out_size)
{
    const float* cb   = (const float*)d_in[0];
    const float* attn = (const float*)d_in[1];
    const int*   idx  = (const int*)d_in[2];
    float*       out  = (float*)d_out;

    dotzero_kernel<<<DOT_CTAS + ZERO_CTAS, 256>>>(cb, attn, out);

    cudaLaunchConfig_t cfg = {};
    cfg.gridDim  = dim3((BT * KS / 4) / 256, 1, 1);    // 1024
    cfg.blockDim = dim3(256, 1, 1);
    cudaLaunchAttribute attrs[1];
    attrs[0].id = cudaLaunchAttributeProgrammaticStreamSerialization;
    attrs[0].val.programmaticStreamSerializationAllowed = 1;
    cfg.attrs = attrs;
    cfg.numAttrs = 1;
    cudaLaunchKernelEx(&cfg, scatter_kernel, idx, out);
}